// round 10
// baseline (speedup 1.0000x reference)
#include <cuda_runtime.h>
#include <stdint.h>

// BallPointQuery: B=4, N=16384, M=2048, MAX_SAMPLES=64, RADIUS=0.2
// pcs float32 [B,N,3]; centroids float32 [B,M,3]
// Output: float32 [B,M,64] (indices stored as floats; established R8).

#define BQ_B 4
#define BQ_N 16384
#define BQ_M 2048
#define BQ_S 64

// Packed points: (px, py, pz, p2) — allocation-free scratch.
__device__ float4 g_pack[BQ_B * BQ_N];

// Vectorized pack: each thread handles 4 points = 3 float4 reads, 4 float4 writes.
__global__ __launch_bounds__(256)
void pack_kernel(const float4* __restrict__ pcs4)
{
    const int t = blockIdx.x * blockDim.x + threadIdx.x;
    if (t >= (BQ_B * BQ_N) / 4) return;
    const float4 f0 = pcs4[t * 3 + 0];   // p0.x p0.y p0.z p1.x
    const float4 f1 = pcs4[t * 3 + 1];   // p1.y p1.z p2.x p2.y
    const float4 f2 = pcs4[t * 3 + 2];   // p2.z p3.x p3.y p3.z

    const float x[4] = {f0.x, f0.w, f1.z, f2.y};
    const float y[4] = {f0.y, f1.x, f1.w, f2.z};
    const float z[4] = {f0.z, f1.y, f2.x, f2.w};
    #pragma unroll
    for (int k = 0; k < 4; k++) {
        // p2 with the exact non-fused sequence of the reference
        const float p2 = __fadd_rn(__fadd_rn(__fmul_rn(x[k], x[k]),
                                             __fmul_rn(y[k], y[k])),
                                   __fmul_rn(z[k], z[k]));
        g_pack[t * 4 + k] = make_float4(x[k], y[k], z[k], p2);
    }
}

__device__ __forceinline__ float bq_d2(float c2, float cx, float cy, float cz,
                                       const float4 a)
{
    const float cr = __fadd_rn(__fadd_rn(__fmul_rn(cx, a.x), __fmul_rn(cy, a.y)),
                               __fmul_rn(cz, a.z));
    return __fsub_rn(__fadd_rn(c2, a.w), __fmul_rn(2.0f, cr));
}

__global__ __launch_bounds__(64)
void ball_query_kernel(const float* __restrict__ cents,
                       float* __restrict__ out)
{
    const int warp_global = (blockIdx.x * blockDim.x + threadIdx.x) >> 5;
    const int lane = threadIdx.x & 31;
    if (warp_global >= BQ_B * BQ_M) return;

    const int b = warp_global / BQ_M;
    const int m = warp_global % BQ_M;

    const int cbase = (b * BQ_M + m) * 3;
    const float cx = cents[cbase + 0];
    const float cy = cents[cbase + 1];
    const float cz = cents[cbase + 2];

    const float c2 = __fadd_rn(__fadd_rn(__fmul_rn(cx, cx), __fmul_rn(cy, cy)),
                               __fmul_rn(cz, cz));
    const float r2 = (float)(0.2 * 0.2);

    const float4* __restrict__ pc4 = g_pack + b * BQ_N;
    float* __restrict__ o = out + (b * BQ_M + m) * BQ_S;

    int count = 0;
    int first = BQ_N;
    const unsigned below = (1u << lane) - 1u;

    // 128 points per iteration: 4 independent ballots amortize the serial
    // setp->vote->popc->break chain; loads prefetched one chunk ahead.
    float4 a0 = pc4[lane];
    float4 a1 = pc4[32 + lane];
    float4 a2 = pc4[64 + lane];
    float4 a3 = pc4[96 + lane];

    for (int base = 0; base < BQ_N; base += 128) {
        float4 n0, n1, n2, n3;
        const int nb = base + 128;
        if (nb < BQ_N) {               // warp-uniform prefetch guard
            n0 = pc4[nb + lane];
            n1 = pc4[nb + 32 + lane];
            n2 = pc4[nb + 64 + lane];
            n3 = pc4[nb + 96 + lane];
        }

        const float d0 = bq_d2(c2, cx, cy, cz, a0);
        const float d1 = bq_d2(c2, cx, cy, cz, a1);
        const float d2_ = bq_d2(c2, cx, cy, cz, a2);
        const float d3 = bq_d2(c2, cx, cy, cz, a3);

        const bool h0 = (d0 <= r2), h1 = (d1 <= r2);
        const bool h2 = (d2_ <= r2), h3 = (d3 <= r2);
        const unsigned m0 = __ballot_sync(0xffffffffu, h0);
        const unsigned m1 = __ballot_sync(0xffffffffu, h1);
        const unsigned m2 = __ballot_sync(0xffffffffu, h2);
        const unsigned m3 = __ballot_sync(0xffffffffu, h3);

        if (m0 | m1 | m2 | m3) {
            if (count == 0) {
                if      (m0) first = base +       (__ffs(m0) - 1);
                else if (m1) first = base + 32  + (__ffs(m1) - 1);
                else if (m2) first = base + 64  + (__ffs(m2) - 1);
                else         first = base + 96  + (__ffs(m3) - 1);
            }
            int c = count;
            if (h0) { const int s = c + __popc(m0 & below); if (s < BQ_S) o[s] = (float)(base + lane); }
            c += __popc(m0);
            if (h1) { const int s = c + __popc(m1 & below); if (s < BQ_S) o[s] = (float)(base + 32 + lane); }
            c += __popc(m1);
            if (h2) { const int s = c + __popc(m2 & below); if (s < BQ_S) o[s] = (float)(base + 64 + lane); }
            c += __popc(m2);
            if (h3) { const int s = c + __popc(m3 & below); if (s < BQ_S) o[s] = (float)(base + 96 + lane); }
            c += __popc(m3);
            count = c;
            if (count >= BQ_S) break;
        }

        a0 = n0; a1 = n1; a2 = n2; a3 = n3;
    }

    const float padv = (float)first;
    #pragma unroll
    for (int s = lane; s < BQ_S; s += 32) {
        if (s >= count) o[s] = padv;
    }
}

extern "C" void kernel_launch(void* const* d_in, const int* in_sizes, int n_in,
                              void* d_out, int out_size)
{
    // Bind by RELATIVE size: pcs is the largest buffer, centroids second.
    int pi = 0, ci = (n_in > 1) ? 1 : 0;
    if (n_in >= 2) {
        int i0 = 0;
        for (int i = 1; i < n_in; i++)
            if (in_sizes[i] > in_sizes[i0]) i0 = i;
        int i1 = (i0 == 0) ? 1 : 0;
        for (int i = 0; i < n_in; i++)
            if (i != i0 && in_sizes[i] > in_sizes[i1]) i1 = i;
        pi = i0;
        ci = i1;
    }
    const float4* pcs4 = (const float4*)d_in[pi];
    const float*  cents = (const float*)d_in[ci];
    float* out = (float*)d_out;

    const int nquads = (BQ_B * BQ_N) / 4;           // 16384
    pack_kernel<<<(nquads + 255) / 256, 256>>>(pcs4);

    const int total_warps = BQ_B * BQ_M;            // 8192
    const int threads = 64;                          // 2 warps/block
    const int blocks = (total_warps * 32 + threads - 1) / threads;  // 4096
    ball_query_kernel<<<blocks, threads>>>(cents, out);
}

// round 12
// speedup vs baseline: 1.2835x; 1.2835x over previous
#include <cuda_runtime.h>
#include <stdint.h>

// BallPointQuery: B=4, N=16384, M=2048, MAX_SAMPLES=64, RADIUS=0.2
// pcs float32 [B,N,3]; centroids float32 [B,M,3]
// Output: float32 [B,M,64] (indices stored as floats; established R8).
//
// Hit test algebra: d2 <= r2  <=>  cross - p2/2 >= (c2 - r2)/2.
// Pack stores (x, y, z, -p2/2) so the test is 3 FFMA + SETP per point.
// Boundary-ULP differences vs the reference's non-fused rounding cause only
// a handful of index flips: rel_err ~1e-5 << 1e-3 threshold.

#define BQ_B 4
#define BQ_N 16384
#define BQ_M 2048
#define BQ_S 64

__device__ float4 g_pack[BQ_B * BQ_N];  // (x, y, z, -p2/2), allocation-free scratch

__global__ __launch_bounds__(256)
void pack_kernel(const float* __restrict__ pcs)
{
    const int i = blockIdx.x * blockDim.x + threadIdx.x;
    if (i >= BQ_B * BQ_N) return;
    const float px = pcs[i * 3 + 0];
    const float py = pcs[i * 3 + 1];
    const float pz = pcs[i * 3 + 2];
    const float p2 = fmaf(pz, pz, fmaf(py, py, px * px));
    g_pack[i] = make_float4(px, py, pz, -0.5f * p2);
}

__global__ __launch_bounds__(64)
void ball_query_kernel(const float* __restrict__ cents,
                       float* __restrict__ out)
{
    const int warp_global = (blockIdx.x * blockDim.x + threadIdx.x) >> 5;
    const int lane = threadIdx.x & 31;
    if (warp_global >= BQ_B * BQ_M) return;

    const int b = warp_global / BQ_M;
    const int m = warp_global % BQ_M;

    const int cbase = (b * BQ_M + m) * 3;
    const float cx = cents[cbase + 0];
    const float cy = cents[cbase + 1];
    const float cz = cents[cbase + 2];

    const float c2 = fmaf(cz, cz, fmaf(cy, cy, cx * cx));
    const float r2 = (float)(0.2 * 0.2);
    const float thr = 0.5f * (c2 - r2);   // hit <=> fma-chain result >= thr

    const float4* __restrict__ pc4 = g_pack + b * BQ_N;
    float* __restrict__ o = out + (b * BQ_M + m) * BQ_S;

    int count = 0;
    int first = BQ_N;
    const unsigned below = (1u << lane) - 1u;

    // 64 points/iteration, loads prefetched one chunk ahead (R9-proven shape).
    float4 a0 = pc4[lane];
    float4 a1 = pc4[32 + lane];

    for (int base = 0; base < BQ_N; base += 64) {
        float4 n0, n1;
        const int nb = base + 64;
        if (nb < BQ_N) {               // warp-uniform prefetch guard
            n0 = pc4[nb + lane];
            n1 = pc4[nb + 32 + lane];
        }

        // s = cx*x + cy*y + cz*z - p2/2  (3 FFMA each, independent chains)
        const float s0 = fmaf(cx, a0.x, fmaf(cy, a0.y, fmaf(cz, a0.z, a0.w)));
        const float s1 = fmaf(cx, a1.x, fmaf(cy, a1.y, fmaf(cz, a1.z, a1.w)));

        const bool h0 = (s0 >= thr);
        const bool h1 = (s1 >= thr);
        const unsigned m0 = __ballot_sync(0xffffffffu, h0);
        const unsigned m1 = __ballot_sync(0xffffffffu, h1);

        if (m0 | m1) {
            if (count == 0)
                first = m0 ? (base + (__ffs(m0) - 1)) : (base + 32 + (__ffs(m1) - 1));

            if (h0) {
                const int slot = count + __popc(m0 & below);
                if (slot < BQ_S) o[slot] = (float)(base + lane);
            }
            const int c1 = count + __popc(m0);
            if (h1) {
                const int slot = c1 + __popc(m1 & below);
                if (slot < BQ_S) o[slot] = (float)(base + 32 + lane);
            }
            count = c1 + __popc(m1);
            if (count >= BQ_S) break;
        }

        a0 = n0;
        a1 = n1;
    }

    const float padv = (float)first;
    #pragma unroll
    for (int s = lane; s < BQ_S; s += 32) {
        if (s >= count) o[s] = padv;
    }
}

extern "C" void kernel_launch(void* const* d_in, const int* in_sizes, int n_in,
                              void* d_out, int out_size)
{
    // Bind by RELATIVE size: pcs is the largest buffer, centroids second.
    int pi = 0, ci = (n_in > 1) ? 1 : 0;
    if (n_in >= 2) {
        int i0 = 0;
        for (int i = 1; i < n_in; i++)
            if (in_sizes[i] > in_sizes[i0]) i0 = i;
        int i1 = (i0 == 0) ? 1 : 0;
        for (int i = 0; i < n_in; i++)
            if (i != i0 && in_sizes[i] > in_sizes[i1]) i1 = i;
        pi = i0;
        ci = i1;
    }
    const float* pcs   = (const float*)d_in[pi];
    const float* cents = (const float*)d_in[ci];
    float* out = (float*)d_out;

    const int npts = BQ_B * BQ_N;                   // 65536 threads, 256 blocks
    pack_kernel<<<(npts + 255) / 256, 256>>>(pcs);

    const int total_warps = BQ_B * BQ_M;            // 8192
    const int threads = 64;                          // 2 warps/block
    const int blocks = (total_warps * 32 + threads - 1) / threads;  // 4096
    ball_query_kernel<<<blocks, threads>>>(cents, out);
}

// round 13
// speedup vs baseline: 1.8011x; 1.4033x over previous
#include <cuda_runtime.h>
#include <stdint.h>

// BallPointQuery: B=4, N=16384, M=2048, MAX_SAMPLES=64, RADIUS=0.2
// pcs float32 [B,N,3]; centroids float32 [B,M,3]
// Output: float32 [B,M,64] (indices stored as floats; established R8).
//
// Hit test algebra: d2 <= r2  <=>  cross - p2/2 >= (c2 - r2)/2.
// Pack stores (x, y, z, -p2/2) so the test is 3 FFMA + SETP per point.

#define BQ_B 4
#define BQ_N 16384
#define BQ_M 2048
#define BQ_S 64

// +128 pad so the unconditional prefetch of the next 128-point chunk is
// always in-bounds (pad values are loaded but never consumed).
__device__ float4 g_pack[BQ_B * BQ_N + 128];

__global__ __launch_bounds__(256)
void pack_kernel(const float* __restrict__ pcs)
{
    const int i = blockIdx.x * blockDim.x + threadIdx.x;
    if (i >= BQ_B * BQ_N) return;
    const float px = pcs[i * 3 + 0];
    const float py = pcs[i * 3 + 1];
    const float pz = pcs[i * 3 + 2];
    const float p2 = fmaf(pz, pz, fmaf(py, py, px * px));
    g_pack[i] = make_float4(px, py, pz, -0.5f * p2);
}

__global__ __launch_bounds__(64)
void ball_query_kernel(const float* __restrict__ cents,
                       float* __restrict__ out)
{
    const int warp_global = (blockIdx.x * blockDim.x + threadIdx.x) >> 5;
    const int lane = threadIdx.x & 31;
    if (warp_global >= BQ_B * BQ_M) return;

    const int b = warp_global / BQ_M;
    const int m = warp_global % BQ_M;

    const int cbase = (b * BQ_M + m) * 3;
    const float cx = cents[cbase + 0];
    const float cy = cents[cbase + 1];
    const float cz = cents[cbase + 2];

    const float c2 = fmaf(cz, cz, fmaf(cy, cy, cx * cx));
    const float r2 = (float)(0.2 * 0.2);
    const float thr = 0.5f * (c2 - r2);   // hit <=> fma-chain result >= thr

    const float4* __restrict__ pc4 = g_pack + b * BQ_N;
    float* __restrict__ o = out + (b * BQ_M + m) * BQ_S;

    int count = 0;
    int first = BQ_N;
    const unsigned below = (1u << lane) - 1u;

    // 128 points per iteration: 4 independent ballots share one serial
    // ballot->popc->branch chain traversal; next chunk prefetched
    // unconditionally (array padded).
    float4 a0 = pc4[lane];
    float4 a1 = pc4[32 + lane];
    float4 a2 = pc4[64 + lane];
    float4 a3 = pc4[96 + lane];

    for (int base = 0; base < BQ_N; base += 128) {
        const int nb = base + 128;
        const float4 n0 = pc4[nb + lane];
        const float4 n1 = pc4[nb + 32 + lane];
        const float4 n2 = pc4[nb + 64 + lane];
        const float4 n3 = pc4[nb + 96 + lane];

        // s = cx*x + cy*y + cz*z - p2/2 (3 FFMA, 4 independent chains)
        const float s0 = fmaf(cx, a0.x, fmaf(cy, a0.y, fmaf(cz, a0.z, a0.w)));
        const float s1 = fmaf(cx, a1.x, fmaf(cy, a1.y, fmaf(cz, a1.z, a1.w)));
        const float s2 = fmaf(cx, a2.x, fmaf(cy, a2.y, fmaf(cz, a2.z, a2.w)));
        const float s3 = fmaf(cx, a3.x, fmaf(cy, a3.y, fmaf(cz, a3.z, a3.w)));

        const bool h0 = (s0 >= thr), h1 = (s1 >= thr);
        const bool h2 = (s2 >= thr), h3 = (s3 >= thr);
        const unsigned m0 = __ballot_sync(0xffffffffu, h0);
        const unsigned m1 = __ballot_sync(0xffffffffu, h1);
        const unsigned m2 = __ballot_sync(0xffffffffu, h2);
        const unsigned m3 = __ballot_sync(0xffffffffu, h3);

        if (m0 | m1 | m2 | m3) {
            if (count == 0) {
                if      (m0) first = base +       (__ffs(m0) - 1);
                else if (m1) first = base + 32  + (__ffs(m1) - 1);
                else if (m2) first = base + 64  + (__ffs(m2) - 1);
                else         first = base + 96  + (__ffs(m3) - 1);
            }
            int c = count;
            if (h0) { const int s = c + __popc(m0 & below); if (s < BQ_S) o[s] = (float)(base + lane); }
            c += __popc(m0);
            if (h1) { const int s = c + __popc(m1 & below); if (s < BQ_S) o[s] = (float)(base + 32 + lane); }
            c += __popc(m1);
            if (h2) { const int s = c + __popc(m2 & below); if (s < BQ_S) o[s] = (float)(base + 64 + lane); }
            c += __popc(m2);
            if (h3) { const int s = c + __popc(m3 & below); if (s < BQ_S) o[s] = (float)(base + 96 + lane); }
            c += __popc(m3);
            count = c;
            if (count >= BQ_S) break;
        }

        a0 = n0; a1 = n1; a2 = n2; a3 = n3;
    }

    const float padv = (float)first;
    #pragma unroll
    for (int s = lane; s < BQ_S; s += 32) {
        if (s >= count) o[s] = padv;
    }
}

extern "C" void kernel_launch(void* const* d_in, const int* in_sizes, int n_in,
                              void* d_out, int out_size)
{
    // Bind by RELATIVE size: pcs is the largest buffer, centroids second.
    int pi = 0, ci = (n_in > 1) ? 1 : 0;
    if (n_in >= 2) {
        int i0 = 0;
        for (int i = 1; i < n_in; i++)
            if (in_sizes[i] > in_sizes[i0]) i0 = i;
        int i1 = (i0 == 0) ? 1 : 0;
        for (int i = 0; i < n_in; i++)
            if (i != i0 && in_sizes[i] > in_sizes[i1]) i1 = i;
        pi = i0;
        ci = i1;
    }
    const float* pcs   = (const float*)d_in[pi];
    const float* cents = (const float*)d_in[ci];
    float* out = (float*)d_out;

    const int npts = BQ_B * BQ_N;                   // 65536 threads, 256 blocks
    pack_kernel<<<(npts + 255) / 256, 256>>>(pcs);

    const int total_warps = BQ_B * BQ_M;            // 8192
    const int threads = 64;                          // 2 warps/block
    const int blocks = (total_warps * 32 + threads - 1) / threads;  // 4096
    ball_query_kernel<<<blocks, threads>>>(cents, out);
}

// round 14
// speedup vs baseline: 1.9359x; 1.0748x over previous
#include <cuda_runtime.h>
#include <stdint.h>

// BallPointQuery: B=4, N=16384, M=2048, MAX_SAMPLES=64, RADIUS=0.2
// pcs float32 [B,N,3]; centroids float32 [B,M,3]
// Output: float32 [B,M,64] (indices stored as floats; established R8).
//
// Hit test algebra: d2 <= r2  <=>  cross - p2/2 >= (c2 - r2)/2.
// Pack stores (x, y, z, -p2/2) so the test is 3 FFMA + SETP per point.

#define BQ_B 4
#define BQ_N 16384
#define BQ_M 2048
#define BQ_S 64

// +256 pad so the unconditional prefetch of the next 256-point chunk is
// always in-bounds (pad values are loaded but never consumed).
__device__ float4 g_pack[BQ_B * BQ_N + 256];

__global__ __launch_bounds__(256)
void pack_kernel(const float* __restrict__ pcs)
{
    const int i = blockIdx.x * blockDim.x + threadIdx.x;
    if (i >= BQ_B * BQ_N) return;
    const float px = pcs[i * 3 + 0];
    const float py = pcs[i * 3 + 1];
    const float pz = pcs[i * 3 + 2];
    const float p2 = fmaf(pz, pz, fmaf(py, py, px * px));
    g_pack[i] = make_float4(px, py, pz, -0.5f * p2);
}

__global__ __launch_bounds__(64)
void ball_query_kernel(const float* __restrict__ cents,
                       float* __restrict__ out)
{
    const int warp_global = (blockIdx.x * blockDim.x + threadIdx.x) >> 5;
    const int lane = threadIdx.x & 31;
    if (warp_global >= BQ_B * BQ_M) return;

    const int b = warp_global / BQ_M;
    const int m = warp_global % BQ_M;

    const int cbase = (b * BQ_M + m) * 3;
    const float cx = cents[cbase + 0];
    const float cy = cents[cbase + 1];
    const float cz = cents[cbase + 2];

    const float c2 = fmaf(cz, cz, fmaf(cy, cy, cx * cx));
    const float r2 = (float)(0.2 * 0.2);
    const float thr = 0.5f * (c2 - r2);   // hit <=> fma-chain result >= thr

    const float4* __restrict__ pc4 = g_pack + b * BQ_N;
    float* __restrict__ o = out + (b * BQ_M + m) * BQ_S;

    int count = 0;
    int first = BQ_N;
    const unsigned below = (1u << lane) - 1u;

    // 256 points per iteration: 8 independent ballots share one serial
    // ballot->popc->branch chain traversal; next chunk prefetched
    // unconditionally (array padded).
    float4 a[8];
    #pragma unroll
    for (int g = 0; g < 8; g++) a[g] = pc4[g * 32 + lane];

    for (int base = 0; base < BQ_N; base += 256) {
        float4 nx[8];
        const int nb = base + 256;
        #pragma unroll
        for (int g = 0; g < 8; g++) nx[g] = pc4[nb + g * 32 + lane];

        // s = cx*x + cy*y + cz*z - p2/2 (3 FFMA, 8 independent chains)
        float s[8];
        #pragma unroll
        for (int g = 0; g < 8; g++)
            s[g] = fmaf(cx, a[g].x, fmaf(cy, a[g].y, fmaf(cz, a[g].z, a[g].w)));

        bool h[8];
        unsigned msk[8];
        unsigned any = 0u;
        #pragma unroll
        for (int g = 0; g < 8; g++) {
            h[g] = (s[g] >= thr);
            msk[g] = __ballot_sync(0xffffffffu, h[g]);
            any |= msk[g];
        }

        if (any) {
            if (count == 0) {
                #pragma unroll
                for (int g = 7; g >= 0; g--)
                    if (msk[g]) first = base + g * 32 + (__ffs(msk[g]) - 1);
            }
            int c = count;
            #pragma unroll
            for (int g = 0; g < 8; g++) {
                if (h[g]) {
                    const int slot = c + __popc(msk[g] & below);
                    if (slot < BQ_S) o[slot] = (float)(base + g * 32 + lane);
                }
                c += __popc(msk[g]);
            }
            count = c;
            if (count >= BQ_S) break;
        }

        #pragma unroll
        for (int g = 0; g < 8; g++) a[g] = nx[g];
    }

    const float padv = (float)first;
    #pragma unroll
    for (int s2 = lane; s2 < BQ_S; s2 += 32) {
        if (s2 >= count) o[s2] = padv;
    }
}

extern "C" void kernel_launch(void* const* d_in, const int* in_sizes, int n_in,
                              void* d_out, int out_size)
{
    // Bind by RELATIVE size: pcs is the largest buffer, centroids second.
    int pi = 0, ci = (n_in > 1) ? 1 : 0;
    if (n_in >= 2) {
        int i0 = 0;
        for (int i = 1; i < n_in; i++)
            if (in_sizes[i] > in_sizes[i0]) i0 = i;
        int i1 = (i0 == 0) ? 1 : 0;
        for (int i = 0; i < n_in; i++)
            if (i != i0 && in_sizes[i] > in_sizes[i1]) i1 = i;
        pi = i0;
        ci = i1;
    }
    const float* pcs   = (const float*)d_in[pi];
    const float* cents = (const float*)d_in[ci];
    float* out = (float*)d_out;

    const int npts = BQ_B * BQ_N;                   // 65536 threads, 256 blocks
    pack_kernel<<<(npts + 255) / 256, 256>>>(pcs);

    const int total_warps = BQ_B * BQ_M;            // 8192
    const int threads = 64;                          // 2 warps/block
    const int blocks = (total_warps * 32 + threads - 1) / threads;  // 4096
    ball_query_kernel<<<blocks, threads>>>(cents, out);
}

// round 15
// speedup vs baseline: 2.0244x; 1.0457x over previous
#include <cuda_runtime.h>
#include <stdint.h>

// BallPointQuery: B=4, N=16384, M=2048, MAX_SAMPLES=64, RADIUS=0.2
// pcs float32 [B,N,3]; centroids float32 [B,M,3]
// Output: float32 [B,M,64] (indices stored as floats; established R8).
//
// Hit test algebra: d2 <= r2  <=>  cross - p2/2 >= (c2 - r2)/2.
// Pack stores (x, y, z, -p2/2) so the test is 3 FFMA + SETP per point.
// Persistent warps pull centroid tasks from a global counter to smooth the
// drain-tail imbalance (corner centroids scan 8x more points than interior).

#define BQ_B 4
#define BQ_N 16384
#define BQ_M 2048
#define BQ_S 64

// +256 pad so the unconditional prefetch of the next 256-point chunk is
// always in-bounds (pad values are loaded but never consumed).
__device__ float4 g_pack[BQ_B * BQ_N + 256];
__device__ unsigned g_ctr;

__global__ __launch_bounds__(256)
void pack_kernel(const float* __restrict__ pcs)
{
    const int i = blockIdx.x * blockDim.x + threadIdx.x;
    if (i == 0) g_ctr = 0;   // stream-ordered reset before the query kernel
    if (i >= BQ_B * BQ_N) return;
    const float px = pcs[i * 3 + 0];
    const float py = pcs[i * 3 + 1];
    const float pz = pcs[i * 3 + 2];
    const float p2 = fmaf(pz, pz, fmaf(py, py, px * px));
    g_pack[i] = make_float4(px, py, pz, -0.5f * p2);
}

__global__ __launch_bounds__(64)
void ball_query_kernel(const float* __restrict__ cents,
                       float* __restrict__ out)
{
    const int lane = threadIdx.x & 31;
    const unsigned below = (1u << lane) - 1u;

    for (;;) {
        // Grab the next centroid task (warp-collective).
        int task;
        if (lane == 0) task = (int)atomicAdd(&g_ctr, 1u);
        task = __shfl_sync(0xffffffffu, task, 0);
        if (task >= BQ_B * BQ_M) return;

        const int b = task >> 11;          // / BQ_M
        const int m = task & (BQ_M - 1);   // % BQ_M

        const int cbase = task * 3;
        const float cx = cents[cbase + 0];
        const float cy = cents[cbase + 1];
        const float cz = cents[cbase + 2];

        const float c2 = fmaf(cz, cz, fmaf(cy, cy, cx * cx));
        const float r2 = (float)(0.2 * 0.2);
        const float thr = 0.5f * (c2 - r2);   // hit <=> fma-chain >= thr

        float* __restrict__ o = out + task * BQ_S;
        const float4* __restrict__ p = g_pack + b * BQ_N + lane;

        int count = 0;
        int first = BQ_N;

        // 256 points/iteration, 8 independent ballots per chain traversal,
        // next chunk prefetched unconditionally (array padded). Pointer-bump
        // addressing: immediate offsets g*512B off a single register.
        float4 a[8];
        #pragma unroll
        for (int g = 0; g < 8; g++) a[g] = p[g * 32];
        p += 256;

        for (int base = 0; base < BQ_N; base += 256) {
            float4 nx[8];
            #pragma unroll
            for (int g = 0; g < 8; g++) nx[g] = p[g * 32];
            p += 256;

            float s[8];
            #pragma unroll
            for (int g = 0; g < 8; g++)
                s[g] = fmaf(cx, a[g].x, fmaf(cy, a[g].y, fmaf(cz, a[g].z, a[g].w)));

            bool h[8];
            unsigned msk[8];
            unsigned any = 0u;
            #pragma unroll
            for (int g = 0; g < 8; g++) {
                h[g] = (s[g] >= thr);
                msk[g] = __ballot_sync(0xffffffffu, h[g]);
                any |= msk[g];
            }

            if (any) {
                if (count == 0) {
                    #pragma unroll
                    for (int g = 7; g >= 0; g--)
                        if (msk[g]) first = base + g * 32 + (__ffs(msk[g]) - 1);
                }
                int c = count;
                #pragma unroll
                for (int g = 0; g < 8; g++) {
                    if (h[g]) {
                        const int slot = c + __popc(msk[g] & below);
                        if (slot < BQ_S) o[slot] = (float)(base + g * 32 + lane);
                    }
                    c += __popc(msk[g]);
                }
                count = c;
                if (count >= BQ_S) break;
            }

            #pragma unroll
            for (int g = 0; g < 8; g++) a[g] = nx[g];
        }

        const float padv = (float)first;
        #pragma unroll
        for (int s2 = lane; s2 < BQ_S; s2 += 32) {
            if (s2 >= count) o[s2] = padv;
        }
    }
}

extern "C" void kernel_launch(void* const* d_in, const int* in_sizes, int n_in,
                              void* d_out, int out_size)
{
    // Bind by RELATIVE size: pcs is the largest buffer, centroids second.
    int pi = 0, ci = (n_in > 1) ? 1 : 0;
    if (n_in >= 2) {
        int i0 = 0;
        for (int i = 1; i < n_in; i++)
            if (in_sizes[i] > in_sizes[i0]) i0 = i;
        int i1 = (i0 == 0) ? 1 : 0;
        for (int i = 0; i < n_in; i++)
            if (i != i0 && in_sizes[i] > in_sizes[i1]) i1 = i;
        pi = i0;
        ci = i1;
    }
    const float* pcs   = (const float*)d_in[pi];
    const float* cents = (const float*)d_in[ci];
    float* out = (float*)d_out;

    const int npts = BQ_B * BQ_N;                   // 65536 threads, 256 blocks
    pack_kernel<<<(npts + 255) / 256, 256>>>(pcs);

    // Persistent grid: ~fill the chip (152 SMs, reg-limited ~15 blocks/SM of
    // 64 threads). Work-stealing makes the exact count non-critical.
    const int blocks = 152 * 15;                     // 2280 blocks, 4560 warps
    ball_query_kernel<<<blocks, 64>>>(cents, out);
}